// round 6
// baseline (speedup 1.0000x reference)
#include <cuda_runtime.h>
#include <math.h>

#define BSZ   128
#define TLEN  256
#define NCLS  128
#define WDIM  512
#define UNITS 512
#define JDIM  2048   // 4*UNITS
#define KX    640    // NC+WD (x-part of IN_DIM)

// ---------------- small persistent device scratch (~0.8 MB total) -------------------
__device__ float g_h[2][BSZ * UNITS];   // ping-pong h buffers
__device__ float g_c[BSZ * UNITS];      // cell state (owner-block private)
__device__ float g_wsum[JDIM];          // 1e-5 * colsum of word rows of W
__device__ int   g_idx[BSZ];

// ---------------- accurate fp32 math independent of -use_fast_math ----------------
__device__ __forceinline__ float my_exp(float x) {
    float t = x * 1.4426950408889634f;
    float n = rintf(t);
    float f = t - n;
    float p =             1.5252733e-5f;
    p = fmaf(p, f, 1.5403530e-4f);
    p = fmaf(p, f, 1.3333558e-3f);
    p = fmaf(p, f, 9.6181291e-3f);
    p = fmaf(p, f, 5.5504109e-2f);
    p = fmaf(p, f, 2.4022647e-1f);
    p = fmaf(p, f, 6.9314718e-1f);
    p = fmaf(p, f, 1.0f);
    return ldexpf(p, (int)n);
}
__device__ __forceinline__ float my_sigmoid(float x) {
    return 1.0f / (1.0f + my_exp(-x));
}
__device__ __forceinline__ float my_tanh(float x) {
    if (x >  20.0f) return  1.0f;
    if (x < -20.0f) return -1.0f;
    float e = my_exp(2.0f * x);
    return (e - 1.0f) / (e + 1.0f);
}

// ---------------- init: zero h buffers and cell state (every call) ------------------
__global__ void init_kernel() {
    int i = blockIdx.x * blockDim.x + threadIdx.x;
    if (i < BSZ * UNITS) {
        g_h[0][i] = 0.0f;
        g_h[1][i] = 0.0f;
        g_c[i]    = 0.0f;
    }
}

// ---------------- word-row column sums: g_wsum[j] = 1e-5 * sum_r W[640+r][j] -------
__global__ void wsum_kernel(const float* __restrict__ W) {
    int j = blockIdx.x * blockDim.x + threadIdx.x;
    if (j < JDIM) {
        float s = 0.0f;
        for (int r = 0; r < NCLS; ++r) s += W[(size_t)(KX + r) * JDIM + j];
        g_wsum[j] = 1e-5f * s;
    }
}

// ---------------- one LSTM time step (x-proj fused) ----------------------------------
// 128 blocks = 8 b-tiles (16 b) x 16 u-tiles (32 u across all 4 gates = 128 cols).
// K loop covers 1152 = 640 (x @ W) + 512 (h @ U), in 18 chunks of 64.
__global__ __launch_bounds__(256) void step_kernel(
    int t,
    const float* __restrict__ xc, const float* __restrict__ xw,
    const float* __restrict__ W,  const float* __restrict__ Umat,
    const float* __restrict__ bias)
{
    __shared__ float B_s[64][128];    // [kk][c], c = gate*32 + uu   (32 KB)
    __shared__ float A_s[16][64];     // [b_local][kk]               (4 KB)
    __shared__ float zbuf[16][128];   // z tile                      (8 KB)

    const int tid = threadIdx.x;
    const int blk = blockIdx.x;
    const int b0  = (blk >> 4) * 16;
    const int u0  = (blk & 15) * 32;
    const float* hin  = g_h[t & 1];
    float*       hout = g_h[(t + 1) & 1];

    const int rg = tid >> 6;   // 0..3  -> b rows rg*4 .. rg*4+3
    const int cp = tid & 63;   // columns cp and cp+64

    float acc[4][2];
#pragma unroll
    for (int r = 0; r < 4; ++r) { acc[r][0] = 0.0f; acc[r][1] = 0.0f; }

    for (int kc = 0; kc < 18; ++kc) {
        const int k0 = kc * 64;
        const bool xphase = (k0 < KX);             // chunks 0..9

        {   // B chunk: 64 k-rows x 128 cols of W (xphase) or U
            const float* Bsrc = xphase ? W : Umat;
            const int    krow0 = xphase ? k0 : (k0 - KX);
            for (int i = tid; i < 64 * 32; i += 256) {
                int kk = i >> 5;
                int c  = (i & 31) * 4;
                int g  = c >> 5;
                int uu = c & 31;
                *(float4*)&B_s[kk][c] =
                    *(const float4*)(Bsrc + (size_t)(krow0 + kk) * JDIM + g * 512 + u0 + uu);
            }
        }
        {   // A chunk: 16 b-rows x 64 k of x_t (xphase) or h_prev
            int bl = tid >> 4;
            int kq = tid & 15;
            int b  = b0 + bl;
            float4 v;
            if (xphase) {
                int k = k0 + kq * 4;
                const float* src = (k < NCLS)
                    ? (xc + ((size_t)b * TLEN + t) * NCLS + k)
                    : (xw + ((size_t)b * TLEN + t) * WDIM + (k - NCLS));
                v = *(const float4*)src;
            } else {
                v = *(const float4*)(hin + (size_t)b * UNITS + (k0 - KX) + kq * 4);
            }
            *(float4*)&A_s[bl][kq * 4] = v;
        }
        __syncthreads();
#pragma unroll 16
        for (int kk = 0; kk < 64; ++kk) {
            float u0v = B_s[kk][cp];
            float u1v = B_s[kk][cp + 64];
#pragma unroll
            for (int r = 0; r < 4; ++r) {
                float av = A_s[rg * 4 + r][kk];
                acc[r][0] = fmaf(av, u0v, acc[r][0]);
                acc[r][1] = fmaf(av, u1v, acc[r][1]);
            }
        }
        __syncthreads();
    }
#pragma unroll
    for (int r = 0; r < 4; ++r) {
        zbuf[rg * 4 + r][cp]      = acc[r][0];
        zbuf[rg * 4 + r][cp + 64] = acc[r][1];
    }
    __syncthreads();

    // finalize: gates + cell update for 2 (b,u) pairs per thread
#pragma unroll
    for (int q = 0; q < 2; ++q) {
        int p  = tid + q * 256;
        int bl = p >> 5;
        int uu = p & 31;
        int b  = b0 + bl;
        int widx = (t == 0) ? -1 : g_idx[b];
        float z[4];
#pragma unroll
        for (int g = 0; g < 4; ++g) {
            int j = g * 512 + u0 + uu;
            float wrow = (widx < 0) ? g_wsum[j]
                                    : W[(size_t)(KX + widx) * JDIM + j];
            z[g] = zbuf[bl][g * 32 + uu] + bias[j] + wrow;
        }
        float ig = my_sigmoid(z[0]);
        float fg = my_sigmoid(z[1]);
        float gg = my_tanh(z[2]);
        float og = my_sigmoid(z[3]);
        size_t ci = (size_t)b * UNITS + u0 + uu;
        float cn = fmaf(fg, g_c[ci], ig * gg);
        g_c[ci] = cn;
        hout[ci] = og * my_tanh(cn);
    }
}

// ---------------- logits + argmax for one step ---------------------------------------
// OUTPUT IS WRITTEN AS FLOAT32: indices are exactly representable; the harness's
// __output__ dtype for this problem is hypothesized to be f32 (see analysis).
__global__ __launch_bounds__(256) void argmax_kernel(
    int t, const float* __restrict__ Ws, const float* __restrict__ bsv,
    float* __restrict__ out)
{
    __shared__ float hrow[UNITS];
    __shared__ float lg[NCLS];
    const int b   = blockIdx.x;
    const int tid = threadIdx.x;
    const float* h = g_h[(t + 1) & 1] + (size_t)b * UNITS;

    for (int i = tid; i < UNITS; i += 256) hrow[i] = h[i];
    __syncthreads();

    int m  = tid & 127;
    int kh = (tid >> 7) * 256;   // K split in two halves
    float a = 0.0f;
    for (int k = 0; k < 256; ++k)
        a = fmaf(hrow[kh + k], Ws[(size_t)(kh + k) * NCLS + m], a);
    if (tid >= 128) lg[m] = a;
    __syncthreads();
    if (tid < 128) lg[tid] = lg[tid] + a + bsv[tid];
    __syncthreads();

    if (tid < 32) {
        float bv = -INFINITY; int bi = 0x7fffffff;
        for (int mm = tid; mm < 128; mm += 32) {
            float v = lg[mm];
            if (v > bv) { bv = v; bi = mm; }   // ascending scan -> first index kept
        }
#pragma unroll
        for (int off = 16; off > 0; off >>= 1) {
            float ov = __shfl_down_sync(0xffffffffu, bv, off);
            int   oi = __shfl_down_sync(0xffffffffu, bi, off);
            if (ov > bv || (ov == bv && oi < bi)) { bv = ov; bi = oi; }
        }
        if (tid == 0) {
            g_idx[b] = bi;
            out[(size_t)b * TLEN + t] = (float)bi;   // FLOAT store
        }
    }
}

// ---------------- harness entry ------------------------------------------------------
extern "C" void kernel_launch(void* const* d_in, const int* in_sizes, int n_in,
                              void* d_out, int out_size) {
    (void)out_size;
    const float *xc = 0, *xw = 0, *W = 0, *U = 0, *bb = 0, *Ws = 0, *bs = 0;
    for (int i = 0; i < n_in; ++i) {
        switch (in_sizes[i]) {
            case BSZ*TLEN*NCLS:   xc = (const float*)d_in[i]; break;  // 4,194,304
            case BSZ*TLEN*WDIM:   xw = (const float*)d_in[i]; break;  // 16,777,216
            case (KX+NCLS)*JDIM:  W  = (const float*)d_in[i]; break;  // 1,572,864
            case UNITS*JDIM:      U  = (const float*)d_in[i]; break;  // 1,048,576
            case JDIM:            bb = (const float*)d_in[i]; break;  // 2,048
            case UNITS*NCLS:      Ws = (const float*)d_in[i]; break;  // 65,536
            case NCLS:            bs = (const float*)d_in[i]; break;  // 128
            default: break;
        }
    }
    if (!xc || !xw || !W || !U || !bb || !Ws || !bs) {   // positional fallback
        xc = (const float*)d_in[0]; xw = (const float*)d_in[1];
        W  = (const float*)d_in[2]; U  = (const float*)d_in[3];
        bb = (const float*)d_in[4]; Ws = (const float*)d_in[5];
        bs = (const float*)d_in[6];
    }
    float* out = (float*)d_out;                // [128,256] as float32

    init_kernel<<<(BSZ*UNITS + 255) / 256, 256>>>();
    wsum_kernel<<<(JDIM + 255) / 256, 256>>>(W);
    for (int t = 0; t < TLEN; ++t) {
        step_kernel<<<128, 256>>>(t, xc, xw, W, U, bb);
        argmax_kernel<<<128, 256>>>(t, Ws, bs, out);
    }
}